// round 3
// baseline (speedup 1.0000x reference)
#include <cuda_runtime.h>
#include <cstdint>

#define N_NODES 50000
#define N_REL   16
#define N_BASIS 8
#define D_IN    64
#define D_HID   64
#define N_CLASS 16
#define N_EDGES 800000

// ---------------- device scratch (static, allowed) ----------------
__device__ __align__(16) float g_W1[N_REL * D_IN * D_HID];      // 256 KB
__device__ __align__(16) float g_W2[N_REL * D_HID * N_CLASS];   // 64 KB
__device__ __align__(16) float g_T1[N_REL * N_NODES * D_HID];   // 204.8 MB
__device__ __align__(16) float g_T2[N_REL * N_NODES * N_CLASS]; // 51.2 MB
__device__ __align__(16) float g_h [N_NODES * D_HID];           // 12.8 MB
__device__ __align__(16) int   g_cnt[N_REL * N_NODES];          // 3.2 MB

// ---------------- tiny setup kernels ----------------
__global__ void k_weights(const float* __restrict__ bases1, const float* __restrict__ coeffs1,
                          const float* __restrict__ bases2, const float* __restrict__ coeffs2)
{
    int blk = blockIdx.x;
    int r = blk & 15;
    if (blk < 16) {
        for (int i = threadIdx.x; i < D_IN * D_HID; i += blockDim.x) {
            float s = 0.f;
            #pragma unroll
            for (int b = 0; b < N_BASIS; b++)
                s += coeffs1[r * N_BASIS + b] * bases1[b * D_IN * D_HID + i];
            g_W1[r * D_IN * D_HID + i] = s;
        }
    } else {
        for (int i = threadIdx.x; i < D_HID * N_CLASS; i += blockDim.x) {
            float s = 0.f;
            #pragma unroll
            for (int b = 0; b < N_BASIS; b++)
                s += coeffs2[r * N_BASIS + b] * bases2[b * D_HID * N_CLASS + i];
            g_W2[r * D_HID * N_CLASS + i] = s;
        }
    }
}

__global__ void k_zero_cnt()
{
    int i = blockIdx.x * blockDim.x + threadIdx.x;
    if (i < N_REL * N_NODES) g_cnt[i] = 0;
}

__global__ void k_count(const int* __restrict__ ei, const int* __restrict__ et)
{
    int e = blockIdx.x * blockDim.x + threadIdx.x;
    if (e >= N_EDGES) return;
    int dst = __ldg(&ei[N_EDGES + e]);
    int t   = __ldg(&et[e]);
    atomicAdd(&g_cnt[t * N_NODES + dst], 1);
}

// ---------------- GEMM: T[r] = X @ W_r (r<16), self-term (r==16) ----------------
// 128-node tile, f32x2 packed FMA, skewed smem (conflict-free), thread rows strided by MG.
template<int LAYER>
__global__ __launch_bounds__(256) void k_gemm(const float* __restrict__ Xin,
                                              const float* __restrict__ Wself,
                                              float* __restrict__ selfout_l2)
{
    constexpr int NOUT = (LAYER == 1) ? D_HID : N_CLASS;
    constexpr int TM   = (LAYER == 1) ? 4 : 2;
    constexpr int TO   = (LAYER == 1) ? 8 : 4;
    constexpr int MG   = 128 / TM;          // 32 or 64

    __shared__ float xs[128 * 64];
    __shared__ float ws[64 * NOUT];

    const float* X    = (LAYER == 1) ? Xin  : g_h;
    const float* Wrel = (LAYER == 1) ? g_W1 : g_W2;
    float*       Trel = (LAYER == 1) ? g_T1 : g_T2;
    float*       selfdst = (LAYER == 1) ? g_h : selfout_l2;

    const int r  = blockIdx.y;
    const float* W = (r < N_REL) ? (Wrel + (size_t)r * 64 * NOUT) : Wself;
    const int nb = blockIdx.x * 128;

    // load X tile with skew: xs[m*64 + ((k+m)&63)] = X[m][k]
    for (int i = threadIdx.x; i < 128 * 16; i += 256) {
        int m  = i >> 4;
        int c4 = (i & 15) * 4;
        float4 v = make_float4(0.f, 0.f, 0.f, 0.f);
        int node = nb + m;
        if (node < N_NODES) v = *(const float4*)(X + (size_t)node * 64 + c4);
        if (LAYER == 2) {
            v.x = fmaxf(v.x, 0.f); v.y = fmaxf(v.y, 0.f);
            v.z = fmaxf(v.z, 0.f); v.w = fmaxf(v.w, 0.f);
        }
        xs[m * 64 + ((c4 + 0 + m) & 63)] = v.x;
        xs[m * 64 + ((c4 + 1 + m) & 63)] = v.y;
        xs[m * 64 + ((c4 + 2 + m) & 63)] = v.z;
        xs[m * 64 + ((c4 + 3 + m) & 63)] = v.w;
    }
    // load W tile
    for (int i = threadIdx.x * 4; i < 64 * NOUT; i += 256 * 4) {
        *(float4*)(ws + i) = *(const float4*)(W + i);
    }
    __syncthreads();

    const int mg = threadIdx.x % MG;
    const int og = threadIdx.x / MG;
    const int o0 = og * TO;

    unsigned long long acc[TM][TO / 2];
    #pragma unroll
    for (int i = 0; i < TM; i++)
        #pragma unroll
        for (int j = 0; j < TO / 2; j++) acc[i][j] = 0ull;

    #pragma unroll 16
    for (int k = 0; k < 64; k++) {
        unsigned long long x2[TM];
        #pragma unroll
        for (int i = 0; i < TM; i++) {
            int m = mg + i * MG;
            float xv = xs[m * 64 + ((k + m) & 63)];
            asm("mov.b64 %0, {%1, %1};" : "=l"(x2[i]) : "f"(xv));
        }
        #pragma unroll
        for (int j = 0; j < TO / 2; j++) {
            unsigned long long w2 = *(const unsigned long long*)(ws + k * NOUT + o0 + 2 * j);
            #pragma unroll
            for (int i = 0; i < TM; i++) {
                asm("fma.rn.f32x2 %0, %1, %2, %0;" : "+l"(acc[i][j]) : "l"(x2[i]), "l"(w2));
            }
        }
    }

    float* outbase = (r < N_REL) ? (Trel + ((size_t)r * N_NODES + nb) * NOUT)
                                 : (selfdst + (size_t)nb * NOUT);
    #pragma unroll
    for (int i = 0; i < TM; i++) {
        int m = mg + i * MG;
        if (nb + m < N_NODES) {
            float* op = outbase + (size_t)m * NOUT + o0;
            #pragma unroll
            for (int j = 0; j < TO / 2; j += 2) {
                float2 a = *(float2*)&acc[i][j];
                float2 b = *(float2*)&acc[i][j + 1];
                *(float4*)(op + 2 * j) = make_float4(a.x, a.y, b.x, b.y);
            }
        }
    }
}

// ---------------- edge scatter: dest[dst] += inv_c * T[type][src] ----------------
template<int LAYER>
__global__ void k_scatter(const int* __restrict__ ei,
                          const int* __restrict__ et,
                          float* __restrict__ dest_l2)
{
    constexpr int NOUT = (LAYER == 1) ? D_HID : N_CLASS;
    constexpr int CH   = NOUT / 4;
    const float* T = (LAYER == 1) ? g_T1 : g_T2;
    float* dest    = (LAYER == 1) ? g_h  : dest_l2;

    int idx = blockIdx.x * blockDim.x + threadIdx.x;
    if (idx >= N_EDGES * CH) return;
    int e = idx / CH;
    int c = idx & (CH - 1);

    int src = __ldg(&ei[e]);
    int dst = __ldg(&ei[N_EDGES + e]);
    int t   = __ldg(&et[e]);
    int cnt = __ldg((const int*)&g_cnt[t * N_NODES + dst]);
    float inv = 1.0f / (float)(cnt > 0 ? cnt : 1);

    float4 v = __ldg((const float4*)(T + ((size_t)t * N_NODES + src) * NOUT + c * 4));
    float* p = dest + (size_t)dst * NOUT + c * 4;
    atomicAdd(p + 0, v.x * inv);
    atomicAdd(p + 1, v.y * inv);
    atomicAdd(p + 2, v.z * inv);
    atomicAdd(p + 3, v.w * inv);
}

// ---------------- launch ----------------
extern "C" void kernel_launch(void* const* d_in, const int* in_sizes, int n_in,
                              void* d_out, int out_size)
{
    const float* x       = (const float*)d_in[0];
    const float* bases1  = (const float*)d_in[1];
    const float* coeffs1 = (const float*)d_in[2];
    const float* self1   = (const float*)d_in[3];
    const float* bases2  = (const float*)d_in[4];
    const float* coeffs2 = (const float*)d_in[5];
    const float* self2   = (const float*)d_in[6];
    const int* ei        = (const int*)d_in[7];
    const int* et        = (const int*)d_in[8];
    float* out = (float*)d_out;

    const int NODE_TILES = (N_NODES + 127) / 128;   // 391

    k_weights<<<32, 256>>>(bases1, coeffs1, bases2, coeffs2);
    k_zero_cnt<<<(N_REL * N_NODES + 255) / 256, 256>>>();
    k_count<<<(N_EDGES + 255) / 256, 256>>>(ei, et);

    // layer 1: T1[r] = x @ W1_r ; h = x @ self1 ; then scatter into h
    k_gemm<1><<<dim3(NODE_TILES, N_REL + 1), 256>>>(x, self1, nullptr);
    k_scatter<1><<<(N_EDGES * (D_HID / 4) + 255) / 256, 256>>>(ei, et, nullptr);

    // layer 2: reads relu(h) inside; T2[r] = relu(h) @ W2_r ; out = relu(h) @ self2 ; scatter into out
    k_gemm<2><<<dim3(NODE_TILES, N_REL + 1), 256>>>(nullptr, self2, out);
    k_scatter<2><<<(N_EDGES * (N_CLASS / 4) + 255) / 256, 256>>>(ei, et, out);
}